// round 3
// baseline (speedup 1.0000x reference)
#include <cuda_runtime.h>
#include <math.h>

#define B_    4
#define S_    1024
#define DIM_  2048
#define H_    16
#define HD_   128
#define BSTOT 4096   // B_*S_
#define NSB   8      // S_/128 s-blocks
#define NTRI  36     // NSB*(NSB+1)/2 lower-tri tiles

// ---------------- scratch ----------------
__device__ float d_K[(size_t)H_*B_*S_*HD_];   // K2 = k @ (W W^T)   (H,B,S,HD)
__device__ float d_V[(size_t)H_*B_*S_*HD_];   // V  = v @ W         (H,B,S,HD)
__device__ float d_A[(size_t)H_*S_*S_];       // (H,S,S) lower tri (upper untouched)
__device__ float d_O[(size_t)BSTOT*DIM_];
__device__ float d_G[(size_t)BSTOT*DIM_];
__device__ float d_M[(size_t)H_*HD_*HD_];     // W W^T per head
__device__ float d_suf[(size_t)H_*B_*NSB*HD_];// suffix sums of V at 128-boundaries
__device__ float d_rs[H_*S_];
__device__ float d_l2g[H_];

// ---------------- decay tables ----------------
__global__ void decay_kernel() {
    int h = blockIdx.x;
    int j = threadIdx.x;
    double g  = 1.0 - exp2((double)(-5 - h));
    double r  = 1.0 / g;
    double rp = pow(r, (double)(j + 1));
    double Sj = (rp - 1.0) / (r - 1.0);
    d_rs[h * S_ + j] = (float)(1.0 / sqrt(Sj));
    if (j == 0) d_l2g[h] = (float)log2(g);
}

// ---------------- M = W W^T per head (tiny) ----------------
__global__ void m_kernel(const float* __restrict__ Wh) {
    const int h = blockIdx.x;
    const float* W = Wh + (size_t)h * HD_ * HD_;
    float* M = d_M + (size_t)h * HD_ * HD_;
    for (int it = 0; it < 64; it++) {
        int idx = threadIdx.x + it * 256;      // 0..16383
        int d = idx >> 7, e = idx & 127;
        float s = 0.f;
#pragma unroll 8
        for (int c = 0; c < HD_; c++) s += W[d * HD_ + c] * W[e * HD_ + c];
        M[idx] = s;
    }
}

// ---------------- K2 / V projection ----------------
__global__ void qkv_kernel(const float* __restrict__ kin,
                           const float* __restrict__ vin,
                           const float* __restrict__ Wh) {
    const int h     = blockIdx.y;
    const int which = blockIdx.z;
    const float* src = (which == 0) ? kin : vin;
    const float* Wm  = (which == 0) ? (d_M + (size_t)h * HD_ * HD_)
                                    : (Wh  + (size_t)h * HD_ * HD_);
    float* dst = (which == 0) ? d_K : d_V;
    const int m0 = blockIdx.x * 64;

    __shared__ float Xs[32][65];
    __shared__ float Ws[32][128];

    const int tid = threadIdx.x;
    const int tx = tid & 15, ty = tid >> 4;
    float acc[4][8];
#pragma unroll
    for (int i = 0; i < 4; i++)
#pragma unroll
        for (int j = 0; j < 8; j++) acc[i][j] = 0.0f;

    for (int k0 = 0; k0 < HD_; k0 += 32) {
#pragma unroll
        for (int i = 0; i < 2; i++) {
            int idx = tid + i * 256;
            int r = idx >> 3, c4 = idx & 7;
            int row = m0 + r;
            int b = row >> 10, s = row & 1023;
            float4 vv = *(const float4*)&src[(size_t)(b * S_ + s) * DIM_ + h * HD_ + k0 + c4 * 4];
            Xs[c4 * 4 + 0][r] = vv.x;
            Xs[c4 * 4 + 1][r] = vv.y;
            Xs[c4 * 4 + 2][r] = vv.z;
            Xs[c4 * 4 + 3][r] = vv.w;
        }
#pragma unroll
        for (int i = 0; i < 4; i++) {
            int idx = tid + i * 256;
            int r = idx >> 5, c4 = idx & 31;
            *(float4*)&Ws[r][c4 * 4] = *(const float4*)&Wm[(size_t)(k0 + r) * HD_ + c4 * 4];
        }
        __syncthreads();
#pragma unroll
        for (int kk = 0; kk < 32; kk++) {
            float a[4];
#pragma unroll
            for (int i = 0; i < 4; i++) a[i] = Xs[kk][ty * 4 + i];
            float4 b0 = *(float4*)&Ws[kk][tx * 8];
            float4 b1 = *(float4*)&Ws[kk][tx * 8 + 4];
            float bb[8] = {b0.x, b0.y, b0.z, b0.w, b1.x, b1.y, b1.z, b1.w};
#pragma unroll
            for (int i = 0; i < 4; i++)
#pragma unroll
                for (int j = 0; j < 8; j++) acc[i][j] += a[i] * bb[j];
        }
        __syncthreads();
    }
#pragma unroll
    for (int i = 0; i < 4; i++) {
        int row = m0 + ty * 4 + i;
        int b = row >> 10, s = row & 1023;
        float* drow = dst + ((size_t)(h * B_ + b) * S_ + s) * HD_ + tx * 8;
        float4 o0 = {acc[i][0], acc[i][1], acc[i][2], acc[i][3]};
        float4 o1 = {acc[i][4], acc[i][5], acc[i][6], acc[i][7]};
        *(float4*)&drow[0] = o0;
        *(float4*)&drow[4] = o1;
    }
}

// ---------------- suffix sums of V at 128-row boundaries ----------------
// d_suf[(hb*NSB+i)*HD + e] = sum_{t >= (i+1)*128} V[hb, t, e]
__global__ void suffix_kernel() {
    const int hb = blockIdx.x;            // 0..63
    const int e = threadIdx.x;            // 128
    const float* Vb = d_V + (size_t)hb * S_ * HD_;
    float acc = 0.f;
    for (int i = NSB - 1; i >= 0; i--) {
        d_suf[((size_t)hb * NSB + i) * HD_ + e] = acc;
        const float* blk = Vb + (size_t)i * 128 * HD_;
#pragma unroll 4
        for (int t = 0; t < 128; t++) acc += blk[t * HD_ + e];
    }
}

// ---------------- scores (lower-tri tiles only), 128x128, 8x8 micro ------
// A[h,s,t] = (t>s) ? 1 : max(|SB/sqrt(hd) * gamma^(t-s) * rs[t]|, 1)
// SB[h,s,t] = sum_{b,e} x[b,s,h*HD+e] * K2[h,b,t,e]
__global__ void scores_kernel(const float* __restrict__ x) {
    const int h = blockIdx.y;
    int k = blockIdx.x;
    int si = 0;
    while ((si + 1) * (si + 2) / 2 <= k) si++;
    const int tj = k - si * (si + 1) / 2;
    const int s0 = si * 128, t0 = tj * 128;

    __shared__ float As[16][132];
    __shared__ float Bs[16][132];

    const int tid = threadIdx.x;
    const int tx = tid & 15, ty = tid >> 4;
    float acc[8][8];
#pragma unroll
    for (int i = 0; i < 8; i++)
#pragma unroll
        for (int j = 0; j < 8; j++) acc[i][j] = 0.0f;

    const float* Kh = d_K + (size_t)h * B_ * S_ * HD_;

    for (int kk0 = 0; kk0 < B_ * HD_; kk0 += 16) {
        const int b = kk0 >> 7, e0 = kk0 & 127;
#pragma unroll
        for (int i = 0; i < 2; i++) {
            int idx = tid + i * 256;
            int r = idx >> 2, c4 = idx & 3;
            float4 vv = *(const float4*)&x[(size_t)(b * S_ + s0 + r) * DIM_ + h * HD_ + e0 + c4 * 4];
            As[c4 * 4 + 0][r] = vv.x;
            As[c4 * 4 + 1][r] = vv.y;
            As[c4 * 4 + 2][r] = vv.z;
            As[c4 * 4 + 3][r] = vv.w;
        }
        const float* Kb = Kh + (size_t)b * S_ * HD_;
#pragma unroll
        for (int i = 0; i < 2; i++) {
            int idx = tid + i * 256;
            int r = idx >> 2, c4 = idx & 3;
            float4 vv = *(const float4*)&Kb[(size_t)(t0 + r) * HD_ + e0 + c4 * 4];
            Bs[c4 * 4 + 0][r] = vv.x;
            Bs[c4 * 4 + 1][r] = vv.y;
            Bs[c4 * 4 + 2][r] = vv.z;
            Bs[c4 * 4 + 3][r] = vv.w;
        }
        __syncthreads();
#pragma unroll
        for (int kk = 0; kk < 16; kk++) {
            float4 a0 = *(float4*)&As[kk][ty * 8];
            float4 a1 = *(float4*)&As[kk][ty * 8 + 4];
            float4 b0 = *(float4*)&Bs[kk][tx * 8];
            float4 b1 = *(float4*)&Bs[kk][tx * 8 + 4];
            float a[8]  = {a0.x, a0.y, a0.z, a0.w, a1.x, a1.y, a1.z, a1.w};
            float bb[8] = {b0.x, b0.y, b0.z, b0.w, b1.x, b1.y, b1.z, b1.w};
#pragma unroll
            for (int i = 0; i < 8; i++)
#pragma unroll
                for (int j = 0; j < 8; j++) acc[i][j] += a[i] * bb[j];
        }
        __syncthreads();
    }

    const float l2g = d_l2g[h];
    const float inv_sqrt_hd = 0.08838834764831845f;
    float* Ah = d_A + (size_t)h * S_ * S_;
#pragma unroll
    for (int i = 0; i < 8; i++) {
        int s = s0 + ty * 8 + i;
#pragma unroll
        for (int j = 0; j < 8; j++) {
            int t = t0 + tx * 8 + j;
            float val;
            if (t > s) {
                val = 1.0f;
            } else {
                float dn = exp2f((float)(t - s) * l2g) * d_rs[h * S_ + t];
                val = fmaxf(fabsf(acc[i][j] * inv_sqrt_hd * dn), 1.0f);
            }
            Ah[(size_t)s * S_ + t] = val;
        }
    }
}

// ---------------- O = A_lowtri @ V + suffix, 128x128, 8x8 micro ----------
__global__ void ogemm_kernel() {
    const int bh = blockIdx.y;            // b*H + h
    const int b = bh >> 4, h = bh & 15;
    const int si = blockIdx.x;            // s-block 0..7
    const int s0 = si * 128;
    const int kmax = (si + 1) * 128;      // t-blocks 0..si (diag tile stored incl ones)

    __shared__ float As[16][132];
    __shared__ float Vs[16][128];

    const int tid = threadIdx.x;
    const int tx = tid & 15, ty = tid >> 4;
    float acc[8][8];
#pragma unroll
    for (int i = 0; i < 8; i++)
#pragma unroll
        for (int j = 0; j < 8; j++) acc[i][j] = 0.0f;

    const float* Ah = d_A + (size_t)h * S_ * S_;
    const float* Vb = d_V + ((size_t)h * B_ + b) * S_ * HD_;

    for (int t0 = 0; t0 < kmax; t0 += 16) {
#pragma unroll
        for (int i = 0; i < 2; i++) {
            int idx = tid + i * 256;
            int r = idx >> 2, c4 = idx & 3;
            float4 vv = *(const float4*)&Ah[(size_t)(s0 + r) * S_ + t0 + c4 * 4];
            As[c4 * 4 + 0][r] = vv.x;
            As[c4 * 4 + 1][r] = vv.y;
            As[c4 * 4 + 2][r] = vv.z;
            As[c4 * 4 + 3][r] = vv.w;
        }
#pragma unroll
        for (int i = 0; i < 2; i++) {
            int idx = tid + i * 256;
            int r = idx >> 5, c4 = idx & 31;
            *(float4*)&Vs[r][c4 * 4] = *(const float4*)&Vb[(size_t)(t0 + r) * HD_ + c4 * 4];
        }
        __syncthreads();
#pragma unroll
        for (int kk = 0; kk < 16; kk++) {
            float4 a0 = *(float4*)&As[kk][ty * 8];
            float4 a1 = *(float4*)&As[kk][ty * 8 + 4];
            float4 b0 = *(float4*)&Vs[kk][tx * 8];
            float4 b1 = *(float4*)&Vs[kk][tx * 8 + 4];
            float a[8]  = {a0.x, a0.y, a0.z, a0.w, a1.x, a1.y, a1.z, a1.w};
            float bb[8] = {b0.x, b0.y, b0.z, b0.w, b1.x, b1.y, b1.z, b1.w};
#pragma unroll
            for (int i = 0; i < 8; i++)
#pragma unroll
                for (int j = 0; j < 8; j++) acc[i][j] += a[i] * bb[j];
        }
        __syncthreads();
    }

    // add suffix contribution (all t >= kmax have A == 1)
    const float* suf = d_suf + ((size_t)(h * B_ + b) * NSB + si) * HD_;
    float4 s0v = *(const float4*)&suf[tx * 8];
    float4 s1v = *(const float4*)&suf[tx * 8 + 4];
    float sv[8] = {s0v.x, s0v.y, s0v.z, s0v.w, s1v.x, s1v.y, s1v.z, s1v.w};
#pragma unroll
    for (int i = 0; i < 8; i++)
#pragma unroll
        for (int j = 0; j < 8; j++) acc[i][j] += sv[j];

#pragma unroll
    for (int i = 0; i < 8; i++) {
        int s = s0 + ty * 8 + i;
        float* orow = d_O + (size_t)(b * S_ + s) * DIM_ + h * HD_ + tx * 8;
        float4 o0 = {acc[i][0], acc[i][1], acc[i][2], acc[i][3]};
        float4 o1 = {acc[i][4], acc[i][5], acc[i][6], acc[i][7]};
        *(float4*)&orow[0] = o0;
        *(float4*)&orow[4] = o1;
    }
}

// ---------------- big FF GEMM ----------------
__global__ void ff_kernel(const float* __restrict__ Aparam,
                          const float* __restrict__ Bm,
                          float* __restrict__ Cparam, int mode) {
    const float* Am = (mode == 0) ? Aparam : d_G;
    float* Cm       = (mode == 0) ? d_G : Cparam;

    const int n0 = blockIdx.x * 128;
    const int m0 = blockIdx.y * 128;

    __shared__ float As[16][132];
    __shared__ float Bs[16][128];

    const int tid = threadIdx.x;
    const int tx = tid & 15, ty = tid >> 4;
    float acc[8][8];
#pragma unroll
    for (int i = 0; i < 8; i++)
#pragma unroll
        for (int j = 0; j < 8; j++) acc[i][j] = 0.0f;

    for (int k0 = 0; k0 < DIM_; k0 += 16) {
#pragma unroll
        for (int i = 0; i < 2; i++) {
            int idx = tid + i * 256;
            int r = idx >> 2, c4 = idx & 3;
            float4 vv = *(const float4*)&Am[(size_t)(m0 + r) * DIM_ + k0 + c4 * 4];
            As[c4 * 4 + 0][r] = vv.x;
            As[c4 * 4 + 1][r] = vv.y;
            As[c4 * 4 + 2][r] = vv.z;
            As[c4 * 4 + 3][r] = vv.w;
        }
#pragma unroll
        for (int i = 0; i < 2; i++) {
            int idx = tid + i * 256;
            int r = idx >> 5, c4 = idx & 31;
            *(float4*)&Bs[r][c4 * 4] = *(const float4*)&Bm[(size_t)(k0 + r) * DIM_ + n0 + c4 * 4];
        }
        __syncthreads();
#pragma unroll
        for (int kk = 0; kk < 16; kk++) {
            float4 a0 = *(float4*)&As[kk][ty * 8];
            float4 a1 = *(float4*)&As[kk][ty * 8 + 4];
            float4 b0 = *(float4*)&Bs[kk][tx * 8];
            float4 b1 = *(float4*)&Bs[kk][tx * 8 + 4];
            float a[8]  = {a0.x, a0.y, a0.z, a0.w, a1.x, a1.y, a1.z, a1.w};
            float bb[8] = {b0.x, b0.y, b0.z, b0.w, b1.x, b1.y, b1.z, b1.w};
#pragma unroll
            for (int i = 0; i < 8; i++)
#pragma unroll
                for (int j = 0; j < 8; j++) acc[i][j] += a[i] * bb[j];
        }
        __syncthreads();
    }
#pragma unroll
    for (int i = 0; i < 8; i++) {
        int m = m0 + ty * 8 + i;
        float* crow = Cm + (size_t)m * DIM_ + n0 + tx * 8;
        float4 o0, o1;
        if (mode == 0) {
            o0 = make_float4(fmaxf(acc[i][0], 0.f), fmaxf(acc[i][1], 0.f),
                             fmaxf(acc[i][2], 0.f), fmaxf(acc[i][3], 0.f));
            o1 = make_float4(fmaxf(acc[i][4], 0.f), fmaxf(acc[i][5], 0.f),
                             fmaxf(acc[i][6], 0.f), fmaxf(acc[i][7], 0.f));
        } else {
            o0 = make_float4(acc[i][0], acc[i][1], acc[i][2], acc[i][3]);
            o1 = make_float4(acc[i][4], acc[i][5], acc[i][6], acc[i][7]);
        }
        *(float4*)&crow[0] = o0;
        *(float4*)&crow[4] = o1;
    }
}

// ---------------- layernorm fused with gate mul ----------------
__global__ void gn_kernel(const float* __restrict__ gamma,
                          const float* __restrict__ beta) {
    const int row = blockIdx.x;
    const float* orow = d_O + (size_t)row * DIM_;
    float* grow = d_G + (size_t)row * DIM_;
    const int tid = threadIdx.x;

    float v[8];
#pragma unroll
    for (int i = 0; i < 2; i++) {
        float4 t = *(const float4*)&orow[tid * 8 + i * 4];
        v[i * 4 + 0] = t.x; v[i * 4 + 1] = t.y;
        v[i * 4 + 2] = t.z; v[i * 4 + 3] = t.w;
    }

    __shared__ float red[8];
    __shared__ float s_mu, s_inv;

    float lsum = 0.f;
#pragma unroll
    for (int i = 0; i < 8; i++) lsum += v[i];
#pragma unroll
    for (int off = 16; off > 0; off >>= 1) lsum += __shfl_xor_sync(0xffffffffu, lsum, off);
    if ((tid & 31) == 0) red[tid >> 5] = lsum;
    __syncthreads();
    if (tid == 0) {
        float s = 0.f;
#pragma unroll
        for (int w = 0; w < 8; w++) s += red[w];
        s_mu = s * (1.0f / DIM_);
    }
    __syncthreads();
    const float mu = s_mu;

    float lsq = 0.f;
#pragma unroll
    for (int i = 0; i < 8; i++) {
        float d = v[i] - mu;
        lsq += d * d;
    }
#pragma unroll
    for (int off = 16; off > 0; off >>= 1) lsq += __shfl_xor_sync(0xffffffffu, lsq, off);
    __syncthreads();
    if ((tid & 31) == 0) red[tid >> 5] = lsq;
    __syncthreads();
    if (tid == 0) {
        float s = 0.f;
#pragma unroll
        for (int w = 0; w < 8; w++) s += red[w];
        s_inv = rsqrtf(s * (1.0f / DIM_) + 1e-3f);
    }
    __syncthreads();
    const float inv = s_inv;

#pragma unroll
    for (int i = 0; i < 2; i++) {
        int c0 = tid * 8 + i * 4;
        float4 g4 = *(const float4*)&grow[c0];
        float4 gm = *(const float4*)&gamma[c0];
        float4 bt = *(const float4*)&beta[c0];
        float4 out;
        out.x = g4.x * ((v[i * 4 + 0] - mu) * inv * gm.x + bt.x);
        out.y = g4.y * ((v[i * 4 + 1] - mu) * inv * gm.y + bt.y);
        out.z = g4.z * ((v[i * 4 + 2] - mu) * inv * gm.z + bt.z);
        out.w = g4.w * ((v[i * 4 + 3] - mu) * inv * gm.w + bt.w);
        *(float4*)&grow[c0] = out;
    }
}

// ---------------- launch ----------------
extern "C" void kernel_launch(void* const* d_in, const int* in_sizes, int n_in,
                              void* d_out, int out_size) {
    const float* x     = (const float*)d_in[0];
    const float* k     = (const float*)d_in[1];
    const float* v     = (const float*)d_in[2];
    const float* Wh    = (const float*)d_in[3];
    const float* wg_w  = (const float*)d_in[4];
    const float* wo_w  = (const float*)d_in[5];
    const float* gamma = (const float*)d_in[6];
    const float* beta  = (const float*)d_in[7];
    float* out = (float*)d_out;

    decay_kernel<<<H_, S_>>>();
    m_kernel<<<H_, 256>>>(Wh);
    qkv_kernel<<<dim3(BSTOT / 64, H_, 2), 256>>>(k, v, Wh);     // K2, V
    suffix_kernel<<<H_ * B_, HD_>>>();
    scores_kernel<<<dim3(NTRI, H_), 256>>>(x);                  // lower tri only
    ff_kernel<<<dim3(DIM_ / 128, BSTOT / 128), 256>>>(x, wg_w, out, 0);  // G=relu(x@wg)
    ogemm_kernel<<<dim3(NSB, B_ * H_), 256>>>();
    gn_kernel<<<BSTOT, 256>>>(gamma, beta);
    ff_kernel<<<dim3(DIM_ / 128, BSTOT / 128), 256>>>(x, wo_w, out, 1);  // out=G@wo
}

// round 5
// speedup vs baseline: 2.0769x; 2.0769x over previous
#include <cuda_runtime.h>
#include <math.h>

#define B_    4
#define S_    1024
#define DIM_  2048
#define H_    16
#define HD_   128
#define BSTOT 4096   // B_*S_
#define NSB   8      // S_/128 blocks (suffix granularity)
#define NST   72     // lower-needed (64-row s-tile, 128-col t-tile) pairs per head

// ---------------- scratch ----------------
__device__ float d_Q[(size_t)H_*B_*S_*HD_];   // (H,B,S,HD)
__device__ float d_K[(size_t)H_*B_*S_*HD_];
__device__ float d_V[(size_t)H_*B_*S_*HD_];
__device__ float d_A[(size_t)H_*S_*S_];       // (H,S,S) lower-needed tiles only
__device__ float d_O[(size_t)BSTOT*DIM_];
__device__ float d_G[(size_t)BSTOT*DIM_];
__device__ float d_bsum[(size_t)H_*B_*NSB*HD_]; // per-128-block sums of V
__device__ float d_suf[(size_t)H_*B_*NSB*HD_];  // suffix sums at 128-boundaries
__device__ float d_rs[H_*S_];
__device__ float d_l2g[H_];

// ---------------- decay tables ----------------
__global__ void decay_kernel() {
    int h = blockIdx.x;
    int j = threadIdx.x;
    double g  = 1.0 - exp2((double)(-5 - h));
    double r  = 1.0 / g;
    double rp = pow(r, (double)(j + 1));
    double Sj = (rp - 1.0) / (r - 1.0);
    d_rs[h * S_ + j] = (float)(1.0 / sqrt(Sj));
    if (j == 0) d_l2g[h] = (float)log2(g);
}

// ---------------- QKV projection (R1-proven, a-side vectorized) ----------
__global__ void qkv_kernel(const float* __restrict__ x,
                           const float* __restrict__ kin,
                           const float* __restrict__ vin,
                           const float* __restrict__ Wh) {
    const int h     = blockIdx.y;
    const int which = blockIdx.z;
    const float* src = (which == 0) ? x : (which == 1) ? kin : vin;
    float* dst = (which == 0) ? d_Q : (which == 1) ? d_K : d_V;
    const int m0 = blockIdx.x * 64;

    __shared__ float Xs[32][68];   // padded: rows 272B -> float4-aligned
    __shared__ float Ws[32][128];

    const int tid = threadIdx.x;
    const int tx = tid & 15, ty = tid >> 4;
    float acc[4][8];
#pragma unroll
    for (int i = 0; i < 4; i++)
#pragma unroll
        for (int j = 0; j < 8; j++) acc[i][j] = 0.0f;

    for (int k0 = 0; k0 < HD_; k0 += 32) {
#pragma unroll
        for (int i = 0; i < 2; i++) {
            int idx = tid + i * 256;          // 0..511
            int r = idx >> 3, c4 = idx & 7;
            int row = m0 + r;
            int b = row >> 10, s = row & 1023;
            float4 vv = *(const float4*)&src[(size_t)(b * S_ + s) * DIM_ + h * HD_ + k0 + c4 * 4];
            Xs[c4 * 4 + 0][r] = vv.x;
            Xs[c4 * 4 + 1][r] = vv.y;
            Xs[c4 * 4 + 2][r] = vv.z;
            Xs[c4 * 4 + 3][r] = vv.w;
        }
#pragma unroll
        for (int i = 0; i < 4; i++) {
            int idx = tid + i * 256;          // 0..1023
            int r = idx >> 5, c4 = idx & 31;
            *(float4*)&Ws[r][c4 * 4] =
                *(const float4*)&Wh[((size_t)h * HD_ + k0 + r) * HD_ + c4 * 4];
        }
        __syncthreads();
#pragma unroll
        for (int kk = 0; kk < 32; kk++) {
            float4 a4 = *(float4*)&Xs[kk][ty * 4];
            float a[4] = {a4.x, a4.y, a4.z, a4.w};
            float4 b0 = *(float4*)&Ws[kk][tx * 8];
            float4 b1 = *(float4*)&Ws[kk][tx * 8 + 4];
            float bb[8] = {b0.x, b0.y, b0.z, b0.w, b1.x, b1.y, b1.z, b1.w};
#pragma unroll
            for (int i = 0; i < 4; i++)
#pragma unroll
                for (int j = 0; j < 8; j++) acc[i][j] += a[i] * bb[j];
        }
        __syncthreads();
    }
#pragma unroll
    for (int i = 0; i < 4; i++) {
        int row = m0 + ty * 4 + i;
        int b = row >> 10, s = row & 1023;
        float* drow = dst + ((size_t)(h * B_ + b) * S_ + s) * HD_ + tx * 8;
        float4 o0 = {acc[i][0], acc[i][1], acc[i][2], acc[i][3]};
        float4 o1 = {acc[i][4], acc[i][5], acc[i][6], acc[i][7]};
        *(float4*)&drow[0] = o0;
        *(float4*)&drow[4] = o1;
    }
}

// ---------------- suffix phase A: per-128-block column sums of V ----------
__global__ void bsum_kernel() {
    const int hb = blockIdx.x;            // 0..63
    const int i  = blockIdx.y;            // 0..7
    const int e  = threadIdx.x;           // 0..127
    const float* blk = d_V + ((size_t)hb * S_ + i * 128) * HD_;
    float a0 = 0.f, a1 = 0.f, a2 = 0.f, a3 = 0.f;
#pragma unroll 8
    for (int t = 0; t < 128; t += 4) {
        a0 += blk[(t + 0) * HD_ + e];
        a1 += blk[(t + 1) * HD_ + e];
        a2 += blk[(t + 2) * HD_ + e];
        a3 += blk[(t + 3) * HD_ + e];
    }
    d_bsum[((size_t)hb * NSB + i) * HD_ + e] = (a0 + a1) + (a2 + a3);
}

// ---------------- suffix phase B: exclusive suffix scan over 8 blocks ----
__global__ void sufscan_kernel() {
    const int hb = blockIdx.x;
    const int e  = threadIdx.x;
    float acc = 0.f;
#pragma unroll
    for (int i = NSB - 1; i >= 0; i--) {
        d_suf[((size_t)hb * NSB + i) * HD_ + e] = acc;
        acc += d_bsum[((size_t)hb * NSB + i) * HD_ + e];
    }
}

// ---------------- scores (lower-needed tiles only), R1 64x128 tiles ------
// A[h,s,t] = (t>s) ? 1 : max(|SB/sqrt(hd) * gamma^(t-s) * rs[t]|, 1)
// SB[h,s,t] = sum_{b,e} Q[h,b,s,e]*K[h,b,t,e]   (K-dim 512)
__global__ void scores_kernel() {
    const int h = blockIdx.y;
    // decode tile index -> (si [64-row tile], tj [128-col tile]), tj <= si/2
    int k = blockIdx.x;
    int si = 0;
    while (k >= (si / 2 + 1)) { k -= si / 2 + 1; si++; }
    const int tj = k;
    const int s0 = si * 64, t0 = tj * 128;

    __shared__ float Qs[32][68];
    __shared__ float Ks[32][136];

    const int tid = threadIdx.x;
    const int tx = tid & 15, ty = tid >> 4;
    float acc[4][8];
#pragma unroll
    for (int i = 0; i < 4; i++)
#pragma unroll
        for (int j = 0; j < 8; j++) acc[i][j] = 0.0f;

    const float* Qh = d_Q + (size_t)h * B_ * S_ * HD_;
    const float* Kh = d_K + (size_t)h * B_ * S_ * HD_;

    for (int kk0 = 0; kk0 < B_ * HD_; kk0 += 32) {
        int b = kk0 >> 7, e0 = kk0 & 127;
        const float* Qb = Qh + (size_t)b * S_ * HD_;
        const float* Kb = Kh + (size_t)b * S_ * HD_;
#pragma unroll
        for (int i = 0; i < 2; i++) {
            int idx = tid + i * 256;
            int r = idx >> 3, c4 = idx & 7;
            float4 vv = *(const float4*)&Qb[(size_t)(s0 + r) * HD_ + e0 + c4 * 4];
            Qs[c4 * 4 + 0][r] = vv.x;
            Qs[c4 * 4 + 1][r] = vv.y;
            Qs[c4 * 4 + 2][r] = vv.z;
            Qs[c4 * 4 + 3][r] = vv.w;
        }
#pragma unroll
        for (int i = 0; i < 4; i++) {
            int idx = tid + i * 256;
            int r = idx >> 3, c4 = idx & 7;
            float4 vv = *(const float4*)&Kb[(size_t)(t0 + r) * HD_ + e0 + c4 * 4];
            Ks[c4 * 4 + 0][r] = vv.x;
            Ks[c4 * 4 + 1][r] = vv.y;
            Ks[c4 * 4 + 2][r] = vv.z;
            Ks[c4 * 4 + 3][r] = vv.w;
        }
        __syncthreads();
#pragma unroll
        for (int kk = 0; kk < 32; kk++) {
            float4 a4 = *(float4*)&Qs[kk][ty * 4];
            float a[4] = {a4.x, a4.y, a4.z, a4.w};
            float4 b0 = *(float4*)&Ks[kk][tx * 8];
            float4 b1 = *(float4*)&Ks[kk][tx * 8 + 4];
            float bb[8] = {b0.x, b0.y, b0.z, b0.w, b1.x, b1.y, b1.z, b1.w};
#pragma unroll
            for (int i = 0; i < 4; i++)
#pragma unroll
                for (int j = 0; j < 8; j++) acc[i][j] += a[i] * bb[j];
        }
        __syncthreads();
    }

    const float l2g = d_l2g[h];
    const float inv_sqrt_hd = 0.08838834764831845f;  // 1/sqrt(128)
    float* Ah = d_A + (size_t)h * S_ * S_;
#pragma unroll
    for (int i = 0; i < 4; i++) {
        int s = s0 + ty * 4 + i;
#pragma unroll
        for (int j = 0; j < 8; j++) {
            int t = t0 + tx * 8 + j;
            float val;
            if (t > s) {
                val = 1.0f;
            } else {
                float dn = exp2f((float)(t - s) * l2g) * d_rs[h * S_ + t];
                val = fmaxf(fabsf(acc[i][j] * inv_sqrt_hd * dn), 1.0f);
            }
            Ah[(size_t)s * S_ + t] = val;
        }
    }
}

// ---------------- O = A_lowtri @ V + suffix (R1 structure) ----------------
__global__ void ogemm_kernel() {
    const int bh = blockIdx.y;            // b*H + h
    const int b = bh >> 4, h = bh & 15;
    const int s0 = blockIdx.x * 64;
    const int j128 = s0 >> 7;             // which 128-block the diag lives in
    const int kmax = (j128 + 1) * 128;

    __shared__ float As[32][68];
    __shared__ float Vs[32][128];

    const int tid = threadIdx.x;
    const int tx = tid & 15, ty = tid >> 4;
    float acc[4][8];
#pragma unroll
    for (int i = 0; i < 4; i++)
#pragma unroll
        for (int j = 0; j < 8; j++) acc[i][j] = 0.0f;

    const float* Ah = d_A + (size_t)h * S_ * S_;
    const float* Vb = d_V + ((size_t)h * B_ + b) * S_ * HD_;

    for (int t0 = 0; t0 < kmax; t0 += 32) {
#pragma unroll
        for (int i = 0; i < 2; i++) {
            int idx = tid + i * 256;
            int r = idx >> 3, c4 = idx & 7;
            float4 vv = *(const float4*)&Ah[(size_t)(s0 + r) * S_ + t0 + c4 * 4];
            As[c4 * 4 + 0][r] = vv.x;
            As[c4 * 4 + 1][r] = vv.y;
            As[c4 * 4 + 2][r] = vv.z;
            As[c4 * 4 + 3][r] = vv.w;
        }
#pragma unroll
        for (int i = 0; i < 4; i++) {
            int idx = tid + i * 256;
            int r = idx >> 5, c4 = idx & 31;
            *(float4*)&Vs[r][c4 * 4] =
                *(const float4*)&Vb[(size_t)(t0 + r) * HD_ + c4 * 4];
        }
        __syncthreads();
#pragma unroll
        for (int kk = 0; kk < 32; kk++) {
            float4 a4 = *(float4*)&As[kk][ty * 4];
            float a[4] = {a4.x, a4.y, a4.z, a4.w};
            float4 b0 = *(float4*)&Vs[kk][tx * 8];
            float4 b1 = *(float4*)&Vs[kk][tx * 8 + 4];
            float bb[8] = {b0.x, b0.y, b0.z, b0.w, b1.x, b1.y, b1.z, b1.w};
#pragma unroll
            for (int i = 0; i < 4; i++)
#pragma unroll
                for (int j = 0; j < 8; j++) acc[i][j] += a[i] * bb[j];
        }
        __syncthreads();
    }

    // suffix contribution: all t >= kmax have A == 1
    const float* suf = d_suf + ((size_t)(h * B_ + b) * NSB + j128) * HD_;
    float4 s0v = *(const float4*)&suf[tx * 8];
    float4 s1v = *(const float4*)&suf[tx * 8 + 4];
    float sv[8] = {s0v.x, s0v.y, s0v.z, s0v.w, s1v.x, s1v.y, s1v.z, s1v.w};
#pragma unroll
    for (int i = 0; i < 4; i++)
#pragma unroll
        for (int j = 0; j < 8; j++) acc[i][j] += sv[j];

#pragma unroll
    for (int i = 0; i < 4; i++) {
        int s = s0 + ty * 4 + i;
        float* orow = d_O + (size_t)(b * S_ + s) * DIM_ + h * HD_ + tx * 8;
        float4 o0 = {acc[i][0], acc[i][1], acc[i][2], acc[i][3]};
        float4 o1 = {acc[i][4], acc[i][5], acc[i][6], acc[i][7]};
        *(float4*)&orow[0] = o0;
        *(float4*)&orow[4] = o1;
    }
}

// ---------------- big FF GEMM (R1, aligned padding) ----------------
__global__ void ff_kernel(const float* __restrict__ Aparam,
                          const float* __restrict__ Bm,
                          float* __restrict__ Cparam, int mode) {
    const float* Am = (mode == 0) ? Aparam : d_G;
    float* Cm       = (mode == 0) ? d_G : Cparam;

    const int n0 = blockIdx.x * 128;
    const int m0 = blockIdx.y * 128;

    __shared__ float As[16][136];   // rows 544B -> float4-aligned
    __shared__ float Bs[16][128];

    const int tid = threadIdx.x;
    const int tx = tid & 15, ty = tid >> 4;
    float acc[8][8];
#pragma unroll
    for (int i = 0; i < 8; i++)
#pragma unroll
        for (int j = 0; j < 8; j++) acc[i][j] = 0.0f;

    for (int k0 = 0; k0 < DIM_; k0 += 16) {
#pragma unroll
        for (int i = 0; i < 2; i++) {
            int idx = tid + i * 256;          // 0..511
            int r = idx >> 2, c4 = idx & 3;
            float4 vv = *(const float4*)&Am[(size_t)(m0 + r) * DIM_ + k0 + c4 * 4];
            As[c4 * 4 + 0][r] = vv.x;
            As[c4 * 4 + 1][r] = vv.y;
            As[c4 * 4 + 2][r] = vv.z;
            As[c4 * 4 + 3][r] = vv.w;
        }
#pragma unroll
        for (int i = 0; i < 2; i++) {
            int idx = tid + i * 256;
            int r = idx >> 5, c4 = idx & 31;
            *(float4*)&Bs[r][c4 * 4] =
                *(const float4*)&Bm[(size_t)(k0 + r) * DIM_ + n0 + c4 * 4];
        }
        __syncthreads();
#pragma unroll
        for (int kk = 0; kk < 16; kk++) {
            float4 a0 = *(float4*)&As[kk][ty * 8];
            float4 a1 = *(float4*)&As[kk][ty * 8 + 4];
            float4 b0 = *(float4*)&Bs[kk][tx * 8];
            float4 b1 = *(float4*)&Bs[kk][tx * 8 + 4];
            float a[8]  = {a0.x, a0.y, a0.z, a0.w, a1.x, a1.y, a1.z, a1.w};
            float bb[8] = {b0.x, b0.y, b0.z, b0.w, b1.x, b1.y, b1.z, b1.w};
#pragma unroll
            for (int i = 0; i < 8; i++)
#pragma unroll
                for (int j = 0; j < 8; j++) acc[i][j] += a[i] * bb[j];
        }
        __syncthreads();
    }
#pragma unroll
    for (int i = 0; i < 8; i++) {
        int m = m0 + ty * 8 + i;
        float* crow = Cm + (size_t)m * DIM_ + n0 + tx * 8;
        float4 o0, o1;
        if (mode == 0) {
            o0 = make_float4(fmaxf(acc[i][0], 0.f), fmaxf(acc[i][1], 0.f),
                             fmaxf(acc[i][2], 0.f), fmaxf(acc[i][3], 0.f));
            o1 = make_float4(fmaxf(acc[i][4], 0.f), fmaxf(acc[i][5], 0.f),
                             fmaxf(acc[i][6], 0.f), fmaxf(acc[i][7], 0.f));
        } else {
            o0 = make_float4(acc[i][0], acc[i][1], acc[i][2], acc[i][3]);
            o1 = make_float4(acc[i][4], acc[i][5], acc[i][6], acc[i][7]);
        }
        *(float4*)&crow[0] = o0;
        *(float4*)&crow[4] = o1;
    }
}

// ---------------- layernorm fused with gate mul ----------------
__global__ void gn_kernel(const float* __restrict__ gamma,
                          const float* __restrict__ beta) {
    const int row = blockIdx.x;
    const float* orow = d_O + (size_t)row * DIM_;
    float* grow = d_G + (size_t)row * DIM_;
    const int tid = threadIdx.x;

    float v[8];
#pragma unroll
    for (int i = 0; i < 2; i++) {
        float4 t = *(const float4*)&orow[tid * 8 + i * 4];
        v[i * 4 + 0] = t.x; v[i * 4 + 1] = t.y;
        v[i * 4 + 2] = t.z; v[i * 4 + 3] = t.w;
    }

    __shared__ float red[8];
    __shared__ float s_mu, s_inv;

    float lsum = 0.f;
#pragma unroll
    for (int i = 0; i < 8; i++) lsum += v[i];
#pragma unroll
    for (int off = 16; off > 0; off >>= 1) lsum += __shfl_xor_sync(0xffffffffu, lsum, off);
    if ((tid & 31) == 0) red[tid >> 5] = lsum;
    __syncthreads();
    if (tid == 0) {
        float s = 0.f;
#pragma unroll
        for (int w = 0; w < 8; w++) s += red[w];
        s_mu = s * (1.0f / DIM_);
    }
    __syncthreads();
    const float mu = s_mu;

    float lsq = 0.f;
#pragma unroll
    for (int i = 0; i < 8; i++) {
        float d = v[i] - mu;
        lsq += d * d;
    }
#pragma unroll
    for (int off = 16; off > 0; off >>= 1) lsq += __shfl_xor_sync(0xffffffffu, lsq, off);
    __syncthreads();
    if ((tid & 31) == 0) red[tid >> 5] = lsq;
    __syncthreads();
    if (tid == 0) {
        float s = 0.f;
#pragma unroll
        for (int w = 0; w < 8; w++) s += red[w];
        s_inv = rsqrtf(s * (1.0f / DIM_) + 1e-3f);
    }
    __syncthreads();
    const float inv = s_inv;

#pragma unroll
    for (int i = 0; i < 2; i++) {
        int c0 = tid * 8 + i * 4;
        float4 g4 = *(const float4*)&grow[c0];
        float4 gm = *(const float4*)&gamma[c0];
        float4 bt = *(const float4*)&beta[c0];
        float4 out;
        out.x = g4.x * ((v[i * 4 + 0] - mu) * inv * gm.x + bt.x);
        out.y = g4.y * ((v[i * 4 + 1] - mu) * inv * gm.y + bt.y);
        out.z = g4.z * ((v[i * 4 + 2] - mu) * inv * gm.z + bt.z);
        out.w = g4.w * ((v[i * 4 + 3] - mu) * inv * gm.w + bt.w);
        *(float4*)&grow[c0] = out;
    }
}

// ---------------- launch ----------------
extern "C" void kernel_launch(void* const* d_in, const int* in_sizes, int n_in,
                              void* d_out, int out_size) {
    const float* x     = (const float*)d_in[0];
    const float* k     = (const float*)d_in[1];
    const float* v     = (const float*)d_in[2];
    const float* Wh    = (const float*)d_in[3];
    const float* wg_w  = (const float*)d_in[4];
    const float* wo_w  = (const float*)d_in[5];
    const float* gamma = (const float*)d_in[6];
    const float* beta  = (const float*)d_in[7];
    float* out = (float*)d_out;

    decay_kernel<<<H_, S_>>>();
    qkv_kernel<<<dim3(BSTOT / 64, H_, 3), 256>>>(x, k, v, Wh);
    bsum_kernel<<<dim3(H_ * B_, NSB), HD_>>>();
    sufscan_kernel<<<H_ * B_, HD_>>>();
    scores_kernel<<<dim3(NST, H_), 256>>>();                              // lower tiles only
    ff_kernel<<<dim3(DIM_ / 128, BSTOT / 128), 256>>>(x, wg_w, out, 0);   // G = relu(x@wg)
    ogemm_kernel<<<dim3(S_ / 64, B_ * H_), 256>>>();
    gn_kernel<<<BSTOT, 256>>>(gamma, beta);
    ff_kernel<<<dim3(DIM_ / 128, BSTOT / 128), 256>>>(x, wo_w, out, 1);   // out = G@wo
}